// round 1
// baseline (speedup 1.0000x reference)
#include <cuda_runtime.h>

// BetterBot: 2-layer tiny transformer, B=65536 samples, S=15 tokens, D=8, H=2 heads (hd=4).
// Mapping: 1 token -> 1 lane; 2 samples per warp (16-lane halves); 16 samples / 256-thread block.
// All weights staged in shared (broadcast reads); per-warp k/v staging in shared;
// scores/softmax rows held in registers; mean-pool via shfl.xor within 16-lane groups.

#define TPB 256
#define NW  8   // warps per block
#define SAMPLES_PER_BLOCK (2 * NW)

struct Params {
    const int   *dt, *ds, *sl;
    const float *emb_dice, *emb_star, *emb_btns;
    const float *Wqkv[2], *bqkv[2], *Wo[2], *bo[2], *Wl[2], *bl[2];
    const float *Wout, *bout;
    float *out;
    int B;
};

struct __align__(16) SharedW {
    float Wqkv[2][24][8];
    float bqkv[2][24];
    float Wo[2][8][8];
    float bo[2][8];
    float Wl[2][8][8];
    float bl[2][8];
    float Wout[20][8];
    float bout[20];
    float emb[32][8];   // 0-14 dice, 15-29 star, 30-31 btns
};

__global__ void __launch_bounds__(TPB) bot_kernel(Params p) {
    __shared__ SharedW sw;
    // [warp][half][k=0/v=1][token (padded 17 to de-phase banks)][d]
    __shared__ __align__(16) float skv[NW][2][2][17][8];

    const int tid = threadIdx.x;

    // ---- cooperative weight staging ----
    {
        float *dst = (float *)&sw;
        // layout must match SharedW field order
        const float *srcs[] = {
            p.Wqkv[0], p.Wqkv[1], p.bqkv[0], p.bqkv[1],
            p.Wo[0], p.Wo[1], p.bo[0], p.bo[1],
            p.Wl[0], p.Wl[1], p.bl[0], p.bl[1],
            p.Wout, p.bout,
            p.emb_dice, p.emb_star, p.emb_btns };
        const int lens[] = { 192, 192, 24, 24,
                             64, 64, 8, 8,
                             64, 64, 8, 8,
                             160, 20,
                             120, 120, 16 };
        int off = 0;
        #pragma unroll
        for (int seg = 0; seg < 17; seg++) {
            for (int i = tid; i < lens[seg]; i += TPB)
                dst[off + i] = srcs[seg][i];
            off += lens[seg];
        }
    }
    __syncthreads();

    const int warp = tid >> 5, lane = tid & 31;
    const int half = lane >> 4, s = lane & 15;
    const int b = blockIdx.x * SAMPLES_PER_BLOCK + warp * 2 + half;
    const bool tok = (s < 15);
    const bool valid = (b < p.B);

    // ---- build token embedding x[8] ----
    float x[8];
    #pragma unroll
    for (int j = 0; j < 8; j++) x[j] = 0.f;
    if (tok && valid) {
        int id;
        if (s < 5)       id = p.dt[b * 5 + s];
        else if (s < 10) id = 15 + p.ds[b * 5 + (s - 5)];
        else             id = 30 + p.sl[b * 5 + (s - 10)];
        float4 e0 = *(const float4 *)&sw.emb[id][0];
        float4 e1 = *(const float4 *)&sw.emb[id][4];
        x[0] = e0.x; x[1] = e0.y; x[2] = e0.z; x[3] = e0.w;
        x[4] = e1.x; x[5] = e1.y; x[6] = e1.z; x[7] = e1.w;
    }

    float (*kb)[8] = skv[warp][half][0];
    float (*vb)[8] = skv[warp][half][1];

    #pragma unroll 1
    for (int l = 0; l < 2; l++) {
        __syncwarp();   // protect kv buffer reuse across layers
        // ---- qkv = x @ Wqkv.T + b ----
        float q[8];
        {
            float kv[16];
            #pragma unroll
            for (int j = 0; j < 24; j++) {
                float4 w0 = *(const float4 *)&sw.Wqkv[l][j][0];
                float4 w1 = *(const float4 *)&sw.Wqkv[l][j][4];
                float acc = sw.bqkv[l][j];
                acc += x[0] * w0.x + x[1] * w0.y + x[2] * w0.z + x[3] * w0.w
                     + x[4] * w1.x + x[5] * w1.y + x[6] * w1.z + x[7] * w1.w;
                if (j < 8) q[j] = acc; else kv[j - 8] = acc;
            }
            *(float4 *)&kb[s][0] = make_float4(kv[0], kv[1], kv[2], kv[3]);
            *(float4 *)&kb[s][4] = make_float4(kv[4], kv[5], kv[6], kv[7]);
            *(float4 *)&vb[s][0] = make_float4(kv[8], kv[9], kv[10], kv[11]);
            *(float4 *)&vb[s][4] = make_float4(kv[12], kv[13], kv[14], kv[15]);
        }
        __syncwarp();

        // ---- attention per head (hd=4, scale = 0.5) ----
        float o[8];
        #pragma unroll
        for (int h = 0; h < 2; h++) {
            const int hb = h * 4;
            float q0 = q[hb], q1 = q[hb + 1], q2 = q[hb + 2], q3 = q[hb + 3];
            float sc[15];
            #pragma unroll
            for (int t = 0; t < 15; t++) {
                float4 kk = *(const float4 *)&kb[t][hb];
                sc[t] = 0.5f * (q0 * kk.x + q1 * kk.y + q2 * kk.z + q3 * kk.w);
            }
            float m = sc[0];
            #pragma unroll
            for (int t = 1; t < 15; t++) m = fmaxf(m, sc[t]);
            float sum = 0.f;
            #pragma unroll
            for (int t = 0; t < 15; t++) { sc[t] = __expf(sc[t] - m); sum += sc[t]; }
            float inv = __fdividef(1.f, sum);
            float a0 = 0.f, a1 = 0.f, a2 = 0.f, a3 = 0.f;
            #pragma unroll
            for (int t = 0; t < 15; t++) {
                float w = sc[t] * inv;
                float4 vv = *(const float4 *)&vb[t][hb];
                a0 += w * vv.x; a1 += w * vv.y; a2 += w * vv.z; a3 += w * vv.w;
            }
            o[hb] = a0; o[hb + 1] = a1; o[hb + 2] = a2; o[hb + 3] = a3;
        }

        // ---- o projection + residual ----
        float xo[8];
        #pragma unroll
        for (int j = 0; j < 8; j++) {
            float4 w0 = *(const float4 *)&sw.Wo[l][j][0];
            float4 w1 = *(const float4 *)&sw.Wo[l][j][4];
            xo[j] = x[j] + sw.bo[l][j]
                  + o[0] * w0.x + o[1] * w0.y + o[2] * w0.z + o[3] * w0.w
                  + o[4] * w1.x + o[5] * w1.y + o[6] * w1.z + o[7] * w1.w;
        }
        // ---- linear + relu + residual ----
        #pragma unroll
        for (int j = 0; j < 8; j++) {
            float4 w0 = *(const float4 *)&sw.Wl[l][j][0];
            float4 w1 = *(const float4 *)&sw.Wl[l][j][4];
            float hh = sw.bl[l][j]
                     + xo[0] * w0.x + xo[1] * w0.y + xo[2] * w0.z + xo[3] * w0.w
                     + xo[4] * w1.x + xo[5] * w1.y + xo[6] * w1.z + xo[7] * w1.w;
            x[j] = xo[j] + fmaxf(hh, 0.f);
        }
    }

    // ---- mean pool over 15 tokens (within 16-lane half-warp) ----
    #pragma unroll
    for (int j = 0; j < 8; j++) {
        float v = tok ? x[j] : 0.f;
        v += __shfl_xor_sync(0xffffffffu, v, 1);
        v += __shfl_xor_sync(0xffffffffu, v, 2);
        v += __shfl_xor_sync(0xffffffffu, v, 4);
        v += __shfl_xor_sync(0xffffffffu, v, 8);
        x[j] = v * (1.0f / 15.0f);
    }

    // ---- output projection: lanes 0..15 -> a=s, lanes 0..3 also a=s+16 ----
    if (valid) {
        {
            const int a = s;
            float4 w0 = *(const float4 *)&sw.Wout[a][0];
            float4 w1 = *(const float4 *)&sw.Wout[a][4];
            float r = sw.bout[a]
                    + x[0] * w0.x + x[1] * w0.y + x[2] * w0.z + x[3] * w0.w
                    + x[4] * w1.x + x[5] * w1.y + x[6] * w1.z + x[7] * w1.w;
            p.out[b * 20 + a] = r;
        }
        if (s < 4) {
            const int a = s + 16;
            float4 w0 = *(const float4 *)&sw.Wout[a][0];
            float4 w1 = *(const float4 *)&sw.Wout[a][4];
            float r = sw.bout[a]
                    + x[0] * w0.x + x[1] * w0.y + x[2] * w0.z + x[3] * w0.w
                    + x[4] * w1.x + x[5] * w1.y + x[6] * w1.z + x[7] * w1.w;
            p.out[b * 20 + a] = r;
        }
    }
}

extern "C" void kernel_launch(void* const* d_in, const int* in_sizes, int n_in,
                              void* d_out, int out_size) {
    Params p;
    p.dt = (const int *)d_in[0];
    p.ds = (const int *)d_in[1];
    p.sl = (const int *)d_in[2];
    p.emb_dice = (const float *)d_in[3];
    p.emb_star = (const float *)d_in[4];
    p.emb_btns = (const float *)d_in[5];

    // Input ordering can be either setup_inputs-dict order (Wout@6, bout@7,
    // layer weights at 8..19) or reference-signature order (layers at 6..17,
    // Wout@18, bout@19). Disambiguate by size: Wout has 160 elems, Wqkv0 has 192.
    int layer_base, wout_i, bout_i;
    if (in_sizes[6] == 160) { wout_i = 6; bout_i = 7; layer_base = 8; }
    else                    { layer_base = 6; wout_i = 18; bout_i = 19; }

    for (int l = 0; l < 2; l++) {
        int o = layer_base + 6 * l;
        p.Wqkv[l] = (const float *)d_in[o];
        p.bqkv[l] = (const float *)d_in[o + 1];
        p.Wo[l]   = (const float *)d_in[o + 2];
        p.bo[l]   = (const float *)d_in[o + 3];
        p.Wl[l]   = (const float *)d_in[o + 4];
        p.bl[l]   = (const float *)d_in[o + 5];
    }
    p.Wout = (const float *)d_in[wout_i];
    p.bout = (const float *)d_in[bout_i];
    p.out  = (float *)d_out;
    p.B    = in_sizes[0] / 5;

    int blocks = (p.B + SAMPLES_PER_BLOCK - 1) / SAMPLES_PER_BLOCK;
    bot_kernel<<<blocks, TPB>>>(p);
}

// round 2
// speedup vs baseline: 1.1280x; 1.1280x over previous
#include <cuda_runtime.h>

// BetterBot: 2-layer tiny transformer, B=65536, S=15 tokens, D=8, H=2 (hd=4).
// 1 token -> 1 lane; 2 samples per warp (16-lane halves); 16 samples / 256-thread block.
// Round-2: layer-0 qkv table (32 ids), f32x2-packed math (both heads per packed op),
// no softmax max-subtract, 1/sum folded into output scale.

#define TPB 256
#define NW  8
#define SPB (2 * NW)

typedef unsigned long long u64;

__device__ __forceinline__ u64 pk2(float lo, float hi) {
    u64 r; asm("mov.b64 %0, {%1,%2};" : "=l"(r) : "f"(lo), "f"(hi)); return r;
}
__device__ __forceinline__ void upk2(u64 v, float &lo, float &hi) {
    asm("mov.b64 {%0,%1}, %2;" : "=f"(lo), "=f"(hi) : "l"(v));
}
__device__ __forceinline__ u64 ffma2(u64 a, u64 b, u64 c) {
    u64 d; asm("fma.rn.f32x2 %0, %1, %2, %3;" : "=l"(d) : "l"(a), "l"(b), "l"(c)); return d;
}
__device__ __forceinline__ u64 fmul2(u64 a, u64 b) {
    u64 d; asm("mul.rn.f32x2 %0, %1, %2;" : "=l"(d) : "l"(a), "l"(b)); return d;
}
__device__ __forceinline__ u64 fadd2(u64 a, u64 b) {
    u64 d; asm("add.rn.f32x2 %0, %1, %2;" : "=l"(d) : "l"(a), "l"(b)); return d;
}

struct Params {
    const int   *dt, *ds, *sl;
    const float *emb_dice, *emb_star, *emb_btns;
    const float *Wqkv[2], *bqkv[2], *Wo[2], *bo[2], *Wl[2], *bl[2];
    const float *Wout, *bout;
    float *out;
    int B;
};

struct __align__(16) SW {
    u64 t0[32][12];        // layer-0 qkv table: per id q2[4],k2[4],v2[4] head-interleaved pairs
    u64 Wq1[12][8];        // layer-1 Wqkv, row pairs (r, r+4) within q/k/v groups
    u64 bq1[12];
    u64 Wo2[2][4][8];      // row pairs (2p, 2p+1)
    u64 bo2[2][4];
    u64 Wl2[2][4][8];
    u64 bl2[2][4];
    u64 Wout2[20][4];      // natural adjacent pairs
    float bout[20];
};

// Attention + o-proj + MLP for one layer. q2 head-interleaved pairs (pre-built),
// kb/vb per-half shared buffers (head-interleaved pairs, 48B row stride).
__device__ __forceinline__ void attn_block(
    u64 q2[4], const u64 (*kb)[6], const u64 (*vb)[6],
    float x[8], const u64 (*wo2)[8], const u64 *bo2,
    const u64 (*wl2)[8], const u64 *bl2)
{
    __syncwarp();   // kv writes (all lanes) -> kv reads
    const u64 half2 = pk2(0.5f, 0.5f);
    #pragma unroll
    for (int i = 0; i < 4; i++) q2[i] = fmul2(q2[i], half2);  // fold hd^-0.5 into q

    u64 wt2[15];
    u64 sum2 = 0;
    #pragma unroll
    for (int t = 0; t < 15; t++) {
        ulonglong2 ka = *(const ulonglong2 *)&kb[t][0];
        ulonglong2 kc = *(const ulonglong2 *)&kb[t][2];
        u64 acc = fmul2(q2[0], ka.x);
        acc = ffma2(q2[1], ka.y, acc);
        acc = ffma2(q2[2], kc.x, acc);
        acc = ffma2(q2[3], kc.y, acc);
        float s0, s1; upk2(acc, s0, s1);
        u64 w = pk2(__expf(s0), __expf(s1));
        wt2[t] = w;
        sum2 = (t == 0) ? w : fadd2(sum2, w);
    }
    float sm0, sm1; upk2(sum2, sm0, sm1);
    const u64 inv2 = pk2(__fdividef(1.f, sm0), __fdividef(1.f, sm1));

    u64 av[4];
    {
        ulonglong2 va = *(const ulonglong2 *)&vb[0][0];
        ulonglong2 vc = *(const ulonglong2 *)&vb[0][2];
        av[0] = fmul2(wt2[0], va.x); av[1] = fmul2(wt2[0], va.y);
        av[2] = fmul2(wt2[0], vc.x); av[3] = fmul2(wt2[0], vc.y);
    }
    #pragma unroll
    for (int t = 1; t < 15; t++) {
        ulonglong2 va = *(const ulonglong2 *)&vb[t][0];
        ulonglong2 vc = *(const ulonglong2 *)&vb[t][2];
        av[0] = ffma2(wt2[t], va.x, av[0]); av[1] = ffma2(wt2[t], va.y, av[1]);
        av[2] = ffma2(wt2[t], vc.x, av[2]); av[3] = ffma2(wt2[t], vc.y, av[3]);
    }
    float o[8];
    #pragma unroll
    for (int i = 0; i < 4; i++) { av[i] = fmul2(av[i], inv2); upk2(av[i], o[i], o[i + 4]); }

    // o projection + residual (row pairs 2p,2p+1; o duplicated)
    u64 od[8];
    #pragma unroll
    for (int i = 0; i < 8; i++) od[i] = pk2(o[i], o[i]);
    float xo[8];
    #pragma unroll
    for (int pr = 0; pr < 4; pr++) {
        const ulonglong2 *wp = (const ulonglong2 *)wo2[pr];
        u64 acc = bo2[pr];
        ulonglong2 w01 = wp[0], w23 = wp[1], w45 = wp[2], w67 = wp[3];
        acc = ffma2(od[0], w01.x, acc); acc = ffma2(od[1], w01.y, acc);
        acc = ffma2(od[2], w23.x, acc); acc = ffma2(od[3], w23.y, acc);
        acc = ffma2(od[4], w45.x, acc); acc = ffma2(od[5], w45.y, acc);
        acc = ffma2(od[6], w67.x, acc); acc = ffma2(od[7], w67.y, acc);
        float r0, r1; upk2(acc, r0, r1);
        xo[2 * pr] = x[2 * pr] + r0; xo[2 * pr + 1] = x[2 * pr + 1] + r1;
    }
    // linear + relu + residual
    u64 xod[8];
    #pragma unroll
    for (int i = 0; i < 8; i++) xod[i] = pk2(xo[i], xo[i]);
    #pragma unroll
    for (int pr = 0; pr < 4; pr++) {
        const ulonglong2 *wp = (const ulonglong2 *)wl2[pr];
        u64 acc = bl2[pr];
        ulonglong2 w01 = wp[0], w23 = wp[1], w45 = wp[2], w67 = wp[3];
        acc = ffma2(xod[0], w01.x, acc); acc = ffma2(xod[1], w01.y, acc);
        acc = ffma2(xod[2], w23.x, acc); acc = ffma2(xod[3], w23.y, acc);
        acc = ffma2(xod[4], w45.x, acc); acc = ffma2(xod[5], w45.y, acc);
        acc = ffma2(xod[6], w67.x, acc); acc = ffma2(xod[7], w67.y, acc);
        float r0, r1; upk2(acc, r0, r1);
        x[2 * pr]     = xo[2 * pr]     + fmaxf(r0, 0.f);
        x[2 * pr + 1] = xo[2 * pr + 1] + fmaxf(r1, 0.f);
    }
}

__global__ void __launch_bounds__(TPB) bot_kernel(Params p) {
    __shared__ SW sw;
    // [warp][half][k=0/v=1][token 0..15][6 u64] (48B row stride, 16B aligned; slots 4-5 pad)
    __shared__ __align__(16) u64 kvb[NW][2][2][16][6];

    const int tid = threadIdx.x;

    // ---- stage layer-1 Wqkv interleaved: pair p -> rows (g*8+r, g*8+r+4), g=p/4, r=p%4
    for (int i = tid; i < 96; i += TPB) {
        int pp = i >> 3, j = i & 7;
        int g = pp >> 2, r = pp & 3;
        int r0 = g * 8 + r;
        sw.Wq1[pp][j] = pk2(p.Wqkv[1][r0 * 8 + j], p.Wqkv[1][(r0 + 4) * 8 + j]);
    }
    if (tid < 12) {
        int g = tid >> 2, r = tid & 3; int r0 = g * 8 + r;
        sw.bq1[tid] = pk2(p.bqkv[1][r0], p.bqkv[1][r0 + 4]);
    }
    // ---- Wo2/Wl2: pair pr -> rows (2pr, 2pr+1)
    for (int i = tid; i < 64; i += TPB) {
        int l = i >> 5, rem = i & 31, pr = rem >> 3, j = rem & 7;
        sw.Wo2[l][pr][j] = pk2(p.Wo[l][(2 * pr) * 8 + j], p.Wo[l][(2 * pr + 1) * 8 + j]);
        sw.Wl2[l][pr][j] = pk2(p.Wl[l][(2 * pr) * 8 + j], p.Wl[l][(2 * pr + 1) * 8 + j]);
    }
    if (tid < 8) {
        int l = tid >> 2, pr = tid & 3;
        sw.bo2[l][pr] = pk2(p.bo[l][2 * pr], p.bo[l][2 * pr + 1]);
        sw.bl2[l][pr] = pk2(p.bl[l][2 * pr], p.bl[l][2 * pr + 1]);
    }
    for (int i = tid; i < 80; i += TPB) {
        int a = i >> 2, j = i & 3;
        sw.Wout2[a][j] = pk2(p.Wout[a * 8 + 2 * j], p.Wout[a * 8 + 2 * j + 1]);
    }
    if (tid < 20) sw.bout[tid] = p.bout[tid];
    // ---- layer-0 qkv table: 32 ids x 12 pairs
    for (int i = tid; i < 384; i += TPB) {
        int id = i / 12, pp = i % 12;
        int g = pp >> 2, r = pp & 3;
        int r0 = g * 8 + r, r1 = r0 + 4;
        const float *e = (id < 15) ? p.emb_dice + id * 8
                        : (id < 30) ? p.emb_star + (id - 15) * 8
                                    : p.emb_btns + (id - 30) * 8;
        const float *w0 = p.Wqkv[0] + r0 * 8;
        const float *w1 = p.Wqkv[0] + r1 * 8;
        u64 acc = pk2(p.bqkv[0][r0], p.bqkv[0][r1]);
        #pragma unroll
        for (int j = 0; j < 8; j++)
            acc = ffma2(pk2(e[j], e[j]), pk2(w0[j], w1[j]), acc);
        sw.t0[id][pp] = acc;
    }
    __syncthreads();

    const int warp = tid >> 5, lane = tid & 31;
    const int half = lane >> 4, s = lane & 15;
    const int b = blockIdx.x * SPB + warp * 2 + half;
    const bool tok = (s < 15);

    // token id (lane s==15 acts as a harmless dummy with id 0)
    int id = 0;
    if (tok) {
        if (s < 5)       id = p.dt[b * 5 + s];
        else if (s < 10) id = 15 + p.ds[b * 5 + (s - 5)];
        else             id = 30 + p.sl[b * 5 + (s - 10)];
    }
    const float *e = (id < 15) ? p.emb_dice + id * 8
                    : (id < 30) ? p.emb_star + (id - 15) * 8
                                : p.emb_btns + (id - 30) * 8;
    float x[8];
    {
        float4 e0 = *(const float4 *)(e);
        float4 e1 = *(const float4 *)(e + 4);
        x[0] = e0.x; x[1] = e0.y; x[2] = e0.z; x[3] = e0.w;
        x[4] = e1.x; x[5] = e1.y; x[6] = e1.z; x[7] = e1.w;
    }

    u64 (*kb)[6] = kvb[warp][half][0];
    u64 (*vb)[6] = kvb[warp][half][1];
    u64 q2[4];

    // ---- layer 0: qkv via table lookup ----
    {
        ulonglong2 a0 = *(const ulonglong2 *)&sw.t0[id][0];
        ulonglong2 a1 = *(const ulonglong2 *)&sw.t0[id][2];
        q2[0] = a0.x; q2[1] = a0.y; q2[2] = a1.x; q2[3] = a1.y;
        *(ulonglong2 *)&kb[s][0] = *(const ulonglong2 *)&sw.t0[id][4];
        *(ulonglong2 *)&kb[s][2] = *(const ulonglong2 *)&sw.t0[id][6];
        *(ulonglong2 *)&vb[s][0] = *(const ulonglong2 *)&sw.t0[id][8];
        *(ulonglong2 *)&vb[s][2] = *(const ulonglong2 *)&sw.t0[id][10];
    }
    attn_block(q2, kb, vb, x, sw.Wo2[0], sw.bo2[0], sw.Wl2[0], sw.bl2[0]);

    // ---- layer 1: qkv computed with packed row-pairs ----
    __syncwarp();   // layer-0 kv reads done before overwrite
    {
        u64 xd[8];
        #pragma unroll
        for (int i = 0; i < 8; i++) xd[i] = pk2(x[i], x[i]);
        u64 outp[12];
        #pragma unroll
        for (int pr = 0; pr < 12; pr++) {
            const ulonglong2 *wp = (const ulonglong2 *)sw.Wq1[pr];
            u64 acc = sw.bq1[pr];
            ulonglong2 w01 = wp[0], w23 = wp[1], w45 = wp[2], w67 = wp[3];
            acc = ffma2(xd[0], w01.x, acc); acc = ffma2(xd[1], w01.y, acc);
            acc = ffma2(xd[2], w23.x, acc); acc = ffma2(xd[3], w23.y, acc);
            acc = ffma2(xd[4], w45.x, acc); acc = ffma2(xd[5], w45.y, acc);
            acc = ffma2(xd[6], w67.x, acc); acc = ffma2(xd[7], w67.y, acc);
            outp[pr] = acc;
        }
        q2[0] = outp[0]; q2[1] = outp[1]; q2[2] = outp[2]; q2[3] = outp[3];
        ulonglong2 st;
        st.x = outp[4];  st.y = outp[5];  *(ulonglong2 *)&kb[s][0] = st;
        st.x = outp[6];  st.y = outp[7];  *(ulonglong2 *)&kb[s][2] = st;
        st.x = outp[8];  st.y = outp[9];  *(ulonglong2 *)&vb[s][0] = st;
        st.x = outp[10]; st.y = outp[11]; *(ulonglong2 *)&vb[s][2] = st;
    }
    attn_block(q2, kb, vb, x, sw.Wo2[1], sw.bo2[1], sw.Wl2[1], sw.bl2[1]);

    // ---- mean pool over 15 tokens (16-lane groups) ----
    #pragma unroll
    for (int j = 0; j < 8; j++) {
        float v = tok ? x[j] : 0.f;
        v += __shfl_xor_sync(0xffffffffu, v, 1);
        v += __shfl_xor_sync(0xffffffffu, v, 2);
        v += __shfl_xor_sync(0xffffffffu, v, 4);
        v += __shfl_xor_sync(0xffffffffu, v, 8);
        x[j] = v * (1.0f / 15.0f);
    }

    // ---- output projection ----
    if (b < p.B) {
        u64 xp[4];
        #pragma unroll
        for (int i = 0; i < 4; i++) xp[i] = pk2(x[2 * i], x[2 * i + 1]);
        {
            const ulonglong2 *wp = (const ulonglong2 *)sw.Wout2[s];
            ulonglong2 w01 = wp[0], w23 = wp[1];
            u64 acc = fmul2(xp[0], w01.x);
            acc = ffma2(xp[1], w01.y, acc);
            acc = ffma2(xp[2], w23.x, acc);
            acc = ffma2(xp[3], w23.y, acc);
            float r0, r1; upk2(acc, r0, r1);
            p.out[b * 20 + s] = sw.bout[s] + r0 + r1;
        }
        if (s < 4) {
            const int a = s + 16;
            const ulonglong2 *wp = (const ulonglong2 *)sw.Wout2[a];
            ulonglong2 w01 = wp[0], w23 = wp[1];
            u64 acc = fmul2(xp[0], w01.x);
            acc = ffma2(xp[1], w01.y, acc);
            acc = ffma2(xp[2], w23.x, acc);
            acc = ffma2(xp[3], w23.y, acc);
            float r0, r1; upk2(acc, r0, r1);
            p.out[b * 20 + a] = sw.bout[a] + r0 + r1;
        }
    }
}

extern "C" void kernel_launch(void* const* d_in, const int* in_sizes, int n_in,
                              void* d_out, int out_size) {
    Params p;
    p.dt = (const int *)d_in[0];
    p.ds = (const int *)d_in[1];
    p.sl = (const int *)d_in[2];
    p.emb_dice = (const float *)d_in[3];
    p.emb_star = (const float *)d_in[4];
    p.emb_btns = (const float *)d_in[5];

    int layer_base, wout_i, bout_i;
    if (in_sizes[6] == 160) { wout_i = 6; bout_i = 7; layer_base = 8; }
    else                    { layer_base = 6; wout_i = 18; bout_i = 19; }

    for (int l = 0; l < 2; l++) {
        int o = layer_base + 6 * l;
        p.Wqkv[l] = (const float *)d_in[o];
        p.bqkv[l] = (const float *)d_in[o + 1];
        p.Wo[l]   = (const float *)d_in[o + 2];
        p.bo[l]   = (const float *)d_in[o + 3];
        p.Wl[l]   = (const float *)d_in[o + 4];
        p.bl[l]   = (const float *)d_in[o + 5];
    }
    p.Wout = (const float *)d_in[wout_i];
    p.bout = (const float *)d_in[bout_i];
    p.out  = (float *)d_out;
    p.B    = in_sizes[0] / 5;

    int blocks = (p.B + SPB - 1) / SPB;
    bot_kernel<<<blocks, TPB>>>(p);
}